// round 2
// baseline (speedup 1.0000x reference)
#include <cuda_runtime.h>

#define G    8
#define CG   32
#define CH   256
#define HWP  16384                 // H*W
#define NPIX 262144                // B*H*W

typedef unsigned long long ull;

// scratch: [j][pixel], j=0..7 -> sv (softmax branch per group), j=8..15 -> tv (top-k branch)
__device__ __align__(16) float g_scratch[16 * NPIX];

__device__ __forceinline__ ull pack2(float a, float b) {
    ull r; asm("mov.b64 %0, {%1,%2};" : "=l"(r) : "f"(a), "f"(b)); return r;
}
__device__ __forceinline__ void unpack2(ull v, float& a, float& b) {
    asm("mov.b64 {%0,%1}, %2;" : "=f"(a), "=f"(b) : "l"(v));
}
__device__ __forceinline__ void fma2(ull& d, ull a, ull b) {
    asm("fma.rn.f32x2 %0, %1, %2, %0;" : "+l"(d) : "l"(a), "l"(b));
}

#define NEG_INF __int_as_float(0xff800000)

// ---------------------------------------------------------------------------
// Kernel A: per (group, pixel-pair) -> softmax-weighted dot (sv) and top-4 dot (tv)
// grid = (512, 8), block = 256. Each thread: 1 group x 2 pixels, 32 float2 loads.
// ---------------------------------------------------------------------------
__global__ void __launch_bounds__(256)
stats_kernel(const float* __restrict__ x,
             const float* __restrict__ soft_w1,
             const float* __restrict__ top_w1)
{
    __shared__ float s_w1[CG];
    __shared__ float s_k[4];

    const int g   = blockIdx.y;
    const int tid = threadIdx.x;
    if (tid < CG) s_w1[tid] = __ldg(soft_w1 + g * CG + tid);
    if (tid < 4)  s_k[tid]  = __ldg(top_w1 + g * 4 + tid);
    __syncthreads();

    int t  = blockIdx.x * 256 + tid;   // pixel-pair index
    int p  = t << 1;
    int b  = p >> 14;
    int sp = p & (HWP - 1);
    const float* xg = x + ((size_t)b * CH + (size_t)g * CG) * HWP + sp;

    float es0 = 0.f, es1 = 0.f, ys0 = 0.f, ys1 = 0.f;
    float a0 = NEG_INF, b0 = NEG_INF, c0 = NEG_INF, d0 = NEG_INF;
    float a1 = NEG_INF, b1 = NEG_INF, c1 = NEG_INF, d1 = NEG_INF;

    #pragma unroll 8
    for (int c = 0; c < CG; c++) {
        float2 v = __ldcs((const float2*)(xg + (size_t)c * HWP));
        float w  = s_w1[c];
        {
            float e = __expf(v.x); es0 += e; ys0 = fmaf(v.x * e, w, ys0);
            float f  = fminf(a0, v.x); a0 = fmaxf(a0, v.x);
            float h  = fminf(b0, f);   b0 = fmaxf(b0, f);
            float i2 = fminf(c0, h);   c0 = fmaxf(c0, h);
            d0 = fmaxf(d0, i2);
        }
        {
            float e = __expf(v.y); es1 += e; ys1 = fmaf(v.y * e, w, ys1);
            float f  = fminf(a1, v.y); a1 = fmaxf(a1, v.y);
            float h  = fminf(b1, f);   b1 = fmaxf(b1, f);
            float i2 = fminf(c1, h);   c1 = fmaxf(c1, h);
            d1 = fmaxf(d1, i2);
        }
    }

    float k0 = s_k[0], k1 = s_k[1], k2 = s_k[2], k3 = s_k[3];
    float sv0 = __fdividef(ys0, es0);
    float sv1 = __fdividef(ys1, es1);
    float tv0 = fmaf(a0, k0, fmaf(b0, k1, fmaf(c0, k2, d0 * k3)));
    float tv1 = fmaf(a1, k0, fmaf(b1, k1, fmaf(c1, k2, d1 * k3)));

    *(float2*)(g_scratch + (size_t)g * NPIX + p)       = make_float2(sv0, sv1);
    *(float2*)(g_scratch + (size_t)(8 + g) * NPIX + p) = make_float2(tv0, tv1);
}

// ---------------------------------------------------------------------------
// Kernel B: out[o] = x[o] + sum_j svtv[j] * wc[o][j]   (packed f32x2 FMAs)
// grid = (512, 2), block = 128. Each thread: 4 pixels x 128 channels.
// ---------------------------------------------------------------------------
__global__ void __launch_bounds__(128)
combine_kernel(const float* __restrict__ x,
               const float* __restrict__ soft_w2,
               const float* __restrict__ top_w2,
               const float* __restrict__ rr,
               float* __restrict__ out)
{
    __shared__ __align__(16) ull s_w2[128 * 16];   // per-channel packed (w,w)

    const int tid   = threadIdx.x;
    const int obase = blockIdx.y * 128;

    // branch-mix softmax, folded into w2
    float r0 = __ldg(rr), r1 = __ldg(rr + 1);
    float rm = fmaxf(r0, r1);
    float e0 = __expf(r0 - rm), e1 = __expf(r1 - rm);
    float inv = __frcp_rn(e0 + e1);
    float w_top = e0 * inv, w_soft = e1 * inv;

    #pragma unroll
    for (int i = tid; i < 128 * 16; i += 128) {
        int o = obase + (i >> 4), j = i & 15;
        float w = (j < 8) ? (w_soft * __ldg(soft_w2 + o * G + j))
                          : (w_top  * __ldg(top_w2  + o * G + (j - 8)));
        s_w2[i] = pack2(w, w);
    }

    int q  = blockIdx.x * 128 + tid;   // pixel-quad index
    int p  = q << 2;
    int b  = p >> 14;
    int sp = p & (HWP - 1);

    // load svtv once, packed as pixel pairs (0,1) and (2,3)
    ull s01[16], s23[16];
    #pragma unroll
    for (int j = 0; j < 16; j++) {
        float4 v = *(const float4*)(g_scratch + (size_t)j * NPIX + p);
        s01[j] = pack2(v.x, v.y);
        s23[j] = pack2(v.z, v.w);
    }
    __syncthreads();

    const float* xb = x   + ((size_t)b * CH + obase) * HWP + sp;
    float*       ob = out + ((size_t)b * CH + obase) * HWP + sp;

    #pragma unroll 4
    for (int o = 0; o < 128; o++) {
        float4 xv = __ldcs((const float4*)(xb + (size_t)o * HWP));
        ull acc01 = pack2(xv.x, xv.y);
        ull acc23 = pack2(xv.z, xv.w);
        const ulonglong2* wp = (const ulonglong2*)(s_w2 + (o << 4));
        #pragma unroll
        for (int jj = 0; jj < 8; jj++) {
            ulonglong2 wv = wp[jj];
            fma2(acc01, s01[2 * jj],     wv.x);
            fma2(acc23, s23[2 * jj],     wv.x);
            fma2(acc01, s01[2 * jj + 1], wv.y);
            fma2(acc23, s23[2 * jj + 1], wv.y);
        }
        float4 ov;
        unpack2(acc01, ov.x, ov.y);
        unpack2(acc23, ov.z, ov.w);
        __stcs((float4*)(ob + (size_t)o * HWP), ov);
    }
}

extern "C" void kernel_launch(void* const* d_in, const int* in_sizes, int n_in,
                              void* d_out, int out_size) {
    const float* x   = (const float*)d_in[0];
    const float* sw1 = (const float*)d_in[1];
    const float* sw2 = (const float*)d_in[2];
    const float* tw1 = (const float*)d_in[3];
    const float* tw2 = (const float*)d_in[4];
    const float* r   = (const float*)d_in[5];
    float* out = (float*)d_out;

    // 262144 pixels: A = (pairs/256, groups), B = (quads/128, channel halves)
    stats_kernel<<<dim3(512, 8), 256>>>(x, sw1, tw1);
    combine_kernel<<<dim3(512, 2), 128>>>(x, sw2, tw2, r, out);
}

// round 3
// speedup vs baseline: 1.1433x; 1.1433x over previous
#include <cuda_runtime.h>

#define G    8
#define CG   32
#define CH   256
#define HWP  16384                 // H*W
#define TPB  128

typedef unsigned long long ull;

__device__ __forceinline__ ull pack2(float a, float b) {
    ull r; asm("mov.b64 %0, {%1,%2};" : "=l"(r) : "f"(a), "f"(b)); return r;
}
__device__ __forceinline__ void unpack2(ull v, float& a, float& b) {
    asm("mov.b64 {%0,%1}, %2;" : "=f"(a), "=f"(b) : "l"(v));
}
__device__ __forceinline__ void fma2(ull& d, ull a, ull b) {
    asm("fma.rn.f32x2 %0, %1, %2, %0;" : "+l"(d) : "l"(a), "l"(b));
}

#define NEG_INF __int_as_float(0xff800000)

__global__ void __launch_bounds__(TPB, 6)
cgblock_kernel(const float* __restrict__ x,
               const float* __restrict__ soft_w1,
               const float* __restrict__ soft_w2,
               const float* __restrict__ top_w1,
               const float* __restrict__ top_w2,
               const float* __restrict__ rr,
               float* __restrict__ out)
{
    // packed (w,w) folded second-stage weights: j=0..7 soft, j=8..15 top
    __shared__ __align__(16) ull s_w2[CH * 16];
    __shared__ float s_w1[G * CG];
    __shared__ float s_tw1[G * 4];

    const int tid = threadIdx.x;

    // branch mixing softmax
    float r0 = __ldg(rr), r1 = __ldg(rr + 1);
    float rm = fmaxf(r0, r1);
    float er0 = __expf(r0 - rm), er1 = __expf(r1 - rm);
    float rinv = __frcp_rn(er0 + er1);
    float w_top = er0 * rinv, w_soft = er1 * rinv;

    #pragma unroll 8
    for (int i = tid; i < CH * 16; i += TPB) {
        int o = i >> 4, j = i & 15;
        float w = (j < 8) ? (w_soft * __ldg(soft_w2 + o * G + j))
                          : (w_top  * __ldg(top_w2  + o * G + (j - 8)));
        s_w2[i] = pack2(w, w);
    }
    #pragma unroll
    for (int i = tid; i < G * CG; i += TPB) s_w1[i] = __ldg(soft_w1 + i);
    if (tid < G * 4) s_tw1[tid] = __ldg(top_w1 + tid);
    __syncthreads();

    // pixel-pair per thread, consecutive threads -> consecutive pairs (coalesced)
    int t  = blockIdx.x * TPB + tid;
    int p  = t << 1;
    int b  = p >> 14;
    int sp = p & (HWP - 1);
    const float* xb = x   + (size_t)b * CH * HWP + sp;
    float*       ob = out + (size_t)b * CH * HWP + sp;

    // per-group branch outputs, pixel-pair packed: j=0..7 sv, j=8..15 tv
    ull s01[16];

    #pragma unroll
    for (int g = 0; g < G; g++) {
        const float* xg = xb + g * (CG * HWP);
        float es0 = 0.f, es1 = 0.f, ys0 = 0.f, ys1 = 0.f;
        float a0 = NEG_INF, b0 = NEG_INF, c0 = NEG_INF, d0 = NEG_INF;
        float a1 = NEG_INF, b1 = NEG_INF, c1 = NEG_INF, d1 = NEG_INF;

        #pragma unroll 4
        for (int c = 0; c < CG; c++) {
            float2 v = *(const float2*)(xg + c * HWP);
            float w1 = s_w1[g * CG + c];
            {
                float e = __expf(v.x); es0 += e; ys0 = fmaf(v.x * e, w1, ys0);
                float f  = fminf(a0, v.x); a0 = fmaxf(a0, v.x);
                float h  = fminf(b0, f);   b0 = fmaxf(b0, f);
                float i2 = fminf(c0, h);   c0 = fmaxf(c0, h);
                d0 = fmaxf(d0, i2);
            }
            {
                float e = __expf(v.y); es1 += e; ys1 = fmaf(v.y * e, w1, ys1);
                float f  = fminf(a1, v.y); a1 = fmaxf(a1, v.y);
                float h  = fminf(b1, f);   b1 = fmaxf(b1, f);
                float i2 = fminf(c1, h);   c1 = fmaxf(c1, h);
                d1 = fmaxf(d1, i2);
            }
        }

        float k0 = s_tw1[g * 4 + 0], k1 = s_tw1[g * 4 + 1];
        float k2 = s_tw1[g * 4 + 2], k3 = s_tw1[g * 4 + 3];

        s01[g]     = pack2(__fdividef(ys0, es0), __fdividef(ys1, es1));
        s01[8 + g] = pack2(fmaf(a0, k0, fmaf(b0, k1, fmaf(c0, k2, d0 * k3))),
                           fmaf(a1, k0, fmaf(b1, k1, fmaf(c1, k2, d1 * k3))));
    }

    // Phase 2 (REVERSE channel order for L2 reuse of phase-1's tail):
    // out[o] = x[o] + sum_j svtv[j] * wc[o][j], packed f32x2
    #pragma unroll 4
    for (int o = CH - 1; o >= 0; o--) {
        float2 xv = *(const float2*)(xb + o * HWP);
        ull acc = pack2(xv.x, xv.y);
        const ulonglong2* wp = (const ulonglong2*)(s_w2 + (o << 4));
        #pragma unroll
        for (int jj = 0; jj < 8; jj++) {
            ulonglong2 wv = wp[jj];
            fma2(acc, s01[2 * jj],     wv.x);
            fma2(acc, s01[2 * jj + 1], wv.y);
        }
        float2 ov;
        unpack2(acc, ov.x, ov.y);
        __stcs((float2*)(ob + o * HWP), ov);
    }
}

extern "C" void kernel_launch(void* const* d_in, const int* in_sizes, int n_in,
                              void* d_out, int out_size) {
    const float* x   = (const float*)d_in[0];
    const float* sw1 = (const float*)d_in[1];
    const float* sw2 = (const float*)d_in[2];
    const float* tw1 = (const float*)d_in[3];
    const float* tw2 = (const float*)d_in[4];
    const float* r   = (const float*)d_in[5];
    float* out = (float*)d_out;

    int pixels = out_size / CH;        // 262144
    int pairs  = pixels >> 1;          // 131072
    int blocks = pairs / TPB;          // 1024

    cgblock_kernel<<<blocks, TPB>>>(x, sw1, sw2, tw1, tw2, r, out);
}

// round 4
// speedup vs baseline: 1.3192x; 1.1539x over previous
#include <cuda_runtime.h>

#define G    8
#define CG   32
#define CH   256
#define HWP  16384                 // H*W
#define TPB  128
#define ITERS 2

typedef unsigned long long ull;

__device__ __forceinline__ ull pack2(float a, float b) {
    ull r; asm("mov.b64 %0, {%1,%2};" : "=l"(r) : "f"(a), "f"(b)); return r;
}
__device__ __forceinline__ void unpack2(ull v, float& a, float& b) {
    asm("mov.b64 {%0,%1}, %2;" : "=f"(a), "=f"(b) : "l"(v));
}
__device__ __forceinline__ void fma2(ull& d, ull a, ull b) {
    asm("fma.rn.f32x2 %0, %1, %2, %0;" : "+l"(d) : "l"(a), "l"(b));
}

#define NEG_INF __int_as_float(0xff800000)

__global__ void __launch_bounds__(TPB, 4)
cgblock_kernel(const float* __restrict__ x,
               const float* __restrict__ soft_w1,
               const float* __restrict__ soft_w2,
               const float* __restrict__ top_w1,
               const float* __restrict__ top_w2,
               const float* __restrict__ rr,
               float* __restrict__ out)
{
    __shared__ __align__(16) ull s_w2[CH * 16];   // packed (w,w), j<8 soft, j>=8 top
    __shared__ float s_w1[G * CG];
    __shared__ float s_tw1[G * 4];

    const int tid = threadIdx.x;

    float r0 = __ldg(rr), r1 = __ldg(rr + 1);
    float rm = fmaxf(r0, r1);
    float er0 = __expf(r0 - rm), er1 = __expf(r1 - rm);
    float rinv = __frcp_rn(er0 + er1);
    float w_top = er0 * rinv, w_soft = er1 * rinv;

    #pragma unroll 8
    for (int i = tid; i < CH * 16; i += TPB) {
        int o = i >> 4, j = i & 15;
        float w = (j < 8) ? (w_soft * __ldg(soft_w2 + o * G + j))
                          : (w_top  * __ldg(top_w2  + o * G + (j - 8)));
        s_w2[i] = pack2(w, w);
    }
    #pragma unroll
    for (int i = tid; i < G * CG; i += TPB) s_w1[i] = __ldg(soft_w1 + i);
    if (tid < G * 4) s_tw1[tid] = __ldg(top_w1 + tid);
    __syncthreads();

    for (int it = 0; it < ITERS; it++) {
        // pixel-pair tile: contiguous across grid per iteration (coalesced)
        int t  = it * (gridDim.x * TPB) + blockIdx.x * TPB + tid;
        int p  = t << 1;
        int b  = p >> 14;
        int sp = p & (HWP - 1);
        const float* xb = x   + (size_t)b * CH * HWP + sp;
        float*       ob = out + (size_t)b * CH * HWP + sp;

        ull s01[16];   // j=0..7 sv packed pair, 8..15 tv

        // ---------------- Phase 1: software-pipelined, batches of 8 channels ----
        float2 cur[8], nxt[8];
        #pragma unroll
        for (int i = 0; i < 8; i++) cur[i] = *(const float2*)(xb + (size_t)i * HWP);

        #pragma unroll
        for (int g = 0; g < G; g++) {
            float es0 = 0.f, es1 = 0.f, ys0 = 0.f, ys1 = 0.f;
            float a0 = NEG_INF, b0 = NEG_INF, c0 = NEG_INF, d0 = NEG_INF;
            float a1 = NEG_INF, b1 = NEG_INF, c1 = NEG_INF, d1 = NEG_INF;

            #pragma unroll
            for (int bt = 0; bt < 4; bt++) {
                int nc = g * CG + (bt + 1) * 8;   // next batch's first global channel
                if (nc < CH) {
                    #pragma unroll
                    for (int i = 0; i < 8; i++)
                        nxt[i] = *(const float2*)(xb + (size_t)(nc + i) * HWP);
                }
                #pragma unroll
                for (int i = 0; i < 8; i++) {
                    float2 v = cur[i];
                    float w1 = s_w1[g * CG + bt * 8 + i];
                    {
                        float e = __expf(v.x); es0 += e; ys0 = fmaf(v.x * e, w1, ys0);
                        float f  = fminf(a0, v.x); a0 = fmaxf(a0, v.x);
                        float h  = fminf(b0, f);   b0 = fmaxf(b0, f);
                        float i2 = fminf(c0, h);   c0 = fmaxf(c0, h);
                        d0 = fmaxf(d0, i2);
                    }
                    {
                        float e = __expf(v.y); es1 += e; ys1 = fmaf(v.y * e, w1, ys1);
                        float f  = fminf(a1, v.y); a1 = fmaxf(a1, v.y);
                        float h  = fminf(b1, f);   b1 = fmaxf(b1, f);
                        float i2 = fminf(c1, h);   c1 = fmaxf(c1, h);
                        d1 = fmaxf(d1, i2);
                    }
                }
                #pragma unroll
                for (int i = 0; i < 8; i++) cur[i] = nxt[i];
            }

            float k0 = s_tw1[g * 4 + 0], k1 = s_tw1[g * 4 + 1];
            float k2 = s_tw1[g * 4 + 2], k3 = s_tw1[g * 4 + 3];
            s01[g]     = pack2(__fdividef(ys0, es0), __fdividef(ys1, es1));
            s01[8 + g] = pack2(fmaf(a0, k0, fmaf(b0, k1, fmaf(c0, k2, d0 * k3))),
                               fmaf(a1, k0, fmaf(b1, k1, fmaf(c1, k2, d1 * k3))));
        }

        // ---------------- Phase 2: reverse channels, pipelined batches of 4 -----
        float2 c4[4], n4[4];
        #pragma unroll
        for (int i = 0; i < 4; i++)
            c4[i] = *(const float2*)(xb + (size_t)(CH - 1 - i) * HWP);

        #pragma unroll 4
        for (int ob2 = 0; ob2 < CH / 4; ob2++) {
            if (ob2 < CH / 4 - 1) {
                int nc = CH - 1 - (ob2 + 1) * 4;
                #pragma unroll
                for (int i = 0; i < 4; i++)
                    n4[i] = *(const float2*)(xb + (size_t)(nc - i) * HWP);
            }
            #pragma unroll
            for (int i = 0; i < 4; i++) {
                int o = CH - 1 - ob2 * 4 - i;
                ull acc = pack2(c4[i].x, c4[i].y);
                const ulonglong2* wp = (const ulonglong2*)(s_w2 + (o << 4));
                #pragma unroll
                for (int jj = 0; jj < 8; jj++) {
                    ulonglong2 wv = wp[jj];
                    fma2(acc, s01[2 * jj],     wv.x);
                    fma2(acc, s01[2 * jj + 1], wv.y);
                }
                float2 ov;
                unpack2(acc, ov.x, ov.y);
                __stcs((float2*)(ob + (size_t)o * HWP), ov);
            }
            #pragma unroll
            for (int i = 0; i < 4; i++) c4[i] = n4[i];
        }
    }
}

extern "C" void kernel_launch(void* const* d_in, const int* in_sizes, int n_in,
                              void* d_out, int out_size) {
    const float* x   = (const float*)d_in[0];
    const float* sw1 = (const float*)d_in[1];
    const float* sw2 = (const float*)d_in[2];
    const float* tw1 = (const float*)d_in[3];
    const float* tw2 = (const float*)d_in[4];
    const float* r   = (const float*)d_in[5];
    float* out = (float*)d_out;

    int pixels = out_size / CH;              // 262144
    int pairs  = pixels >> 1;                // 131072
    int blocks = pairs / (TPB * ITERS);      // 512

    cgblock_kernel<<<blocks, TPB>>>(x, sw1, sw2, tw1, tw2, r, out);
}